// round 1
// baseline (speedup 1.0000x reference)
#include <cuda_runtime.h>
#include <math.h>
#include <float.h>

#define NH 8
#define SEQ 4096
#define DH 128
#define LQ 64
#define VTOPK 1024
#define STOPK 2048
#define FORCE_V 30
#define FORCE_S 100
#define SCALE 0.08838834764831845f
#define NW (SEQ / 32)   // 128 mask words per head

// ---------------- device scratch (static: no allocation) ----------------
__device__ float    g_probs[NH * LQ * SEQ];      // 8 MB
__device__ float    g_vert [NH * SEQ];
__device__ float    g_slash[NH * SEQ];
__device__ unsigned g_vbits[NH * NW];
__device__ unsigned g_sbits[NH * NW];

// ---------------- kernel A: softmax probs for last 64 queries ----------------
__global__ void pattern_kernel(const float* __restrict__ q,
                               const float* __restrict__ k) {
    int lq = blockIdx.x;            // 0..63
    int h  = blockIdx.y;            // 0..7
    int qpos = SEQ - LQ + lq;       // 4032 + lq
    __shared__ __align__(16) float qs[DH];
    __shared__ float sc[SEQ];
    __shared__ float red[4];
    int tid  = threadIdx.x;         // 128 threads
    int lane = tid & 31, warp = tid >> 5;

    qs[tid] = q[(h * SEQ + qpos) * DH + tid];
    __syncthreads();

    float4 qv = *(const float4*)&qs[lane * 4];
    for (int j = warp; j < SEQ; j += 4) {
        const float4 kv = *(const float4*)&k[(size_t)(h * SEQ + j) * DH + lane * 4];
        float d = qv.x * kv.x + qv.y * kv.y + qv.z * kv.z + qv.w * kv.w;
        #pragma unroll
        for (int m = 16; m >= 1; m >>= 1) d += __shfl_xor_sync(0xffffffffu, d, m);
        if (lane == 0) sc[j] = (j <= qpos) ? d * SCALE : -FLT_MAX;
    }
    __syncthreads();

    // row max
    float mx = -FLT_MAX;
    for (int j = tid; j < SEQ; j += 128) mx = fmaxf(mx, sc[j]);
    #pragma unroll
    for (int m = 16; m >= 1; m >>= 1) mx = fmaxf(mx, __shfl_xor_sync(0xffffffffu, mx, m));
    if (lane == 0) red[warp] = mx;
    __syncthreads();
    mx = fmaxf(fmaxf(red[0], red[1]), fmaxf(red[2], red[3]));
    __syncthreads();

    // exp + sum
    float sum = 0.f;
    for (int j = tid; j < SEQ; j += 128) {
        float e = expf(sc[j] - mx);
        sc[j] = e;
        sum += e;
    }
    #pragma unroll
    for (int m = 16; m >= 1; m >>= 1) sum += __shfl_xor_sync(0xffffffffu, sum, m);
    if (lane == 0) red[warp] = sum;
    __syncthreads();
    sum = red[0] + red[1] + red[2] + red[3];
    float inv = 1.0f / sum;
    float* dst = &g_probs[(h * LQ + lq) * SEQ];
    for (int j = tid; j < SEQ; j += 128) dst[j] = sc[j] * inv;
}

// ---------------- kernel B: vertical + slash scores ----------------
__global__ void reduce_kernel() {
    int h = blockIdx.x;
    int tid = threadIdx.x;  // 256
    const float* pb = &g_probs[h * LQ * SEQ];

    for (int j = tid; j < SEQ; j += 256) {
        float s = 0.f;
        #pragma unroll 8
        for (int lq = 0; lq < LQ; lq++) s += pb[lq * SEQ + j];
        g_vert[h * SEQ + j] = (j < FORCE_V) ? INFINITY : s;
    }
    for (int d = tid; d < SEQ; d += 256) {
        float s = 0.f;
        #pragma unroll 8
        for (int lq = 0; lq < LQ; lq++) {
            int idx = (SEQ - LQ) + lq - d;
            if (idx >= 0) s += pb[lq * SEQ + idx];
        }
        g_slash[h * SEQ + d] = (d < FORCE_S) ? INFINITY : s;
    }
}

// ---------------- kernel C: exact top-k -> bitmask (jax tie-break) ----------------
__global__ void topk_kernel() {
    int which = blockIdx.x;   // 0 = vertical, 1 = slash
    int h     = blockIdx.y;
    const float* arr = which ? &g_slash[h * SEQ] : &g_vert[h * SEQ];
    unsigned*   bits = which ? &g_sbits[h * NW]  : &g_vbits[h * NW];
    const int K = which ? STOPK : VTOPK;

    __shared__ unsigned long long keys[SEQ];  // 32 KB
    int tid = threadIdx.x;  // 1024 threads

    if (tid < NW) bits[tid] = 0u;
    for (int i = tid; i < SEQ; i += 1024) {
        unsigned vb = __float_as_uint(arr[i]);   // all values positive -> monotonic bits
        keys[i] = ((unsigned long long)vb << 32) | (unsigned)(SEQ - 1 - i);
    }
    __syncthreads();

    // bitonic sort ascending
    for (int kk = 2; kk <= SEQ; kk <<= 1) {
        for (int j = kk >> 1; j > 0; j >>= 1) {
            for (int i = tid; i < SEQ; i += 1024) {
                int ixj = i ^ j;
                if (ixj > i) {
                    unsigned long long a = keys[i], b = keys[ixj];
                    bool up = ((i & kk) == 0);
                    if ((a > b) == up) { keys[i] = b; keys[ixj] = a; }
                }
            }
            __syncthreads();
        }
    }

    // top K = largest keys at the end
    for (int t = tid; t < K; t += 1024) {
        int idx = (SEQ - 1) - (int)(keys[SEQ - 1 - t] & 0xffffffffu);
        atomicOr(&bits[idx >> 5], 1u << (idx & 31));
    }
}

// ---------------- kernel D: masked causal flash attention ----------------
#define SMEM_FLOATS (3 * 64 * 128 + 64 * 64)
#define SMEM_BYTES  (SMEM_FLOATS * 4 + 2 * NW * 4)

__device__ __forceinline__ int swz(int r, int c) {
    // row-major [64][128] floats, float4-chunk XOR swizzle
    return r * 128 + ((c ^ (r >> 2)) << 2);
}

__global__ void __launch_bounds__(256, 1)
flash_kernel(const float* __restrict__ q, const float* __restrict__ k,
             const float* __restrict__ v, float* __restrict__ out) {
    extern __shared__ float smem[];
    float* Qs = smem;               // [64][128] swizzled
    float* Ks = Qs + 64 * 128;
    float* Vs = Ks + 64 * 128;
    float* Ps = Vs + 64 * 128;      // [64][64] chunk^ty swizzled
    unsigned* vb = (unsigned*)(Ps + 64 * 64);
    unsigned* sb = vb + NW;

    int bid = blockIdx.x;
    int h  = bid & 7;
    int it = 63 - (bid >> 3);       // heavy tiles first
    int tid = threadIdx.x;
    int ty = tid >> 4, tx = tid & 15;

    if (tid < NW)            vb[tid]       = g_vbits[h * NW + tid];
    else if (tid < 2 * NW)   sb[tid - NW]  = g_sbits[h * NW + tid - NW];

    const size_t base = (size_t)h * SEQ * DH;
    const int i0 = it * 64;

    // load Q tile (coalesced global, conflict-free swizzled store)
    for (int e = tid; e < 2048; e += 256) {
        int r = e >> 5, c = e & 31;
        *(float4*)&Qs[swz(r, c)] =
            *(const float4*)&q[base + (size_t)(i0 + r) * DH + c * 4];
    }

    float o[4][8];
    float m_i[4], l_i[4];
    #pragma unroll
    for (int a = 0; a < 4; a++) {
        m_i[a] = -FLT_MAX; l_i[a] = 0.f;
        #pragma unroll
        for (int cc = 0; cc < 8; cc++) o[a][cc] = 0.f;
    }

    for (int jt = 0; jt <= it; jt++) {
        const int j0 = jt * 64;
        __syncthreads();
        for (int e = tid; e < 2048; e += 256) {
            int r = e >> 5, c = e & 31;
            size_t g = base + (size_t)(j0 + r) * DH + c * 4;
            *(float4*)&Ks[swz(r, c)] = *(const float4*)&k[g];
            *(float4*)&Vs[swz(r, c)] = *(const float4*)&v[g];
        }
        __syncthreads();

        // ---- QK^T 4x4 micro-tile ----
        float s[4][4];
        #pragma unroll
        for (int a = 0; a < 4; a++)
            #pragma unroll
            for (int b = 0; b < 4; b++) s[a][b] = 0.f;

        #pragma unroll 8
        for (int c = 0; c < 32; c++) {
            float4 qv[4], kv[4];
            #pragma unroll
            for (int a = 0; a < 4; a++) qv[a] = *(const float4*)&Qs[swz(ty * 4 + a, c)];
            #pragma unroll
            for (int b = 0; b < 4; b++) kv[b] = *(const float4*)&Ks[swz(tx * 4 + b, c)];
            #pragma unroll
            for (int a = 0; a < 4; a++)
                #pragma unroll
                for (int b = 0; b < 4; b++)
                    s[a][b] += qv[a].x * kv[b].x + qv[a].y * kv[b].y
                             + qv[a].z * kv[b].z + qv[a].w * kv[b].w;
        }

        // ---- mask + online softmax ----
        #pragma unroll
        for (int a = 0; a < 4; a++) {
            int i_g = i0 + ty * 4 + a;
            float rm = -FLT_MAX;
            #pragma unroll
            for (int b = 0; b < 4; b++) {
                int j_g = j0 + tx * 4 + b;
                int d = i_g - j_g;
                bool ok = (d >= 0) &&
                          (((vb[j_g >> 5] >> (j_g & 31)) & 1u) ||
                           ((sb[d   >> 5] >> (d   & 31)) & 1u));
                float sv = ok ? s[a][b] * SCALE : -FLT_MAX;
                s[a][b] = sv;
                rm = fmaxf(rm, sv);
            }
            #pragma unroll
            for (int m = 1; m < 16; m <<= 1) rm = fmaxf(rm, __shfl_xor_sync(0xffffffffu, rm, m));
            float mn = fmaxf(m_i[a], rm);
            float alpha = __expf(m_i[a] - mn);    // both -FLT_MAX -> exp(0)=1, o==0 so fine
            float rs = 0.f;
            #pragma unroll
            for (int b = 0; b < 4; b++) {
                float p = (mn == -FLT_MAX) ? 0.f : __expf(s[a][b] - mn);
                s[a][b] = p;
                rs += p;
            }
            #pragma unroll
            for (int m = 1; m < 16; m <<= 1) rs += __shfl_xor_sync(0xffffffffu, rs, m);
            l_i[a] = l_i[a] * alpha + rs;
            m_i[a] = mn;
            #pragma unroll
            for (int cc = 0; cc < 8; cc++) o[a][cc] *= alpha;
            *(float4*)&Ps[(ty * 4 + a) * 64 + ((tx ^ ty) << 2)] =
                make_float4(s[a][0], s[a][1], s[a][2], s[a][3]);
        }
        __syncthreads();

        // ---- P @ V ----
        #pragma unroll 4
        for (int kc = 0; kc < 16; kc++) {
            float4 pv[4];
            #pragma unroll
            for (int a = 0; a < 4; a++)
                pv[a] = *(const float4*)&Ps[(ty * 4 + a) * 64 + ((kc ^ ty) << 2)];
            #pragma unroll
            for (int u = 0; u < 4; u++) {
                int kk = kc * 4 + u;
                const float4 v0 = *(const float4*)&Vs[swz(kk, 2 * tx)];
                const float4 v1 = *(const float4*)&Vs[swz(kk, 2 * tx + 1)];
                #pragma unroll
                for (int a = 0; a < 4; a++) {
                    float p = ((const float*)&pv[a])[u];
                    o[a][0] += p * v0.x; o[a][1] += p * v0.y;
                    o[a][2] += p * v0.z; o[a][3] += p * v0.w;
                    o[a][4] += p * v1.x; o[a][5] += p * v1.y;
                    o[a][6] += p * v1.z; o[a][7] += p * v1.w;
                }
            }
        }
    }

    // ---- epilogue ----
    #pragma unroll
    for (int a = 0; a < 4; a++) {
        int i_g = i0 + ty * 4 + a;
        float inv = 1.0f / l_i[a];   // diagonal always allowed -> l > 0
        float4 r0 = make_float4(o[a][0] * inv, o[a][1] * inv, o[a][2] * inv, o[a][3] * inv);
        float4 r1 = make_float4(o[a][4] * inv, o[a][5] * inv, o[a][6] * inv, o[a][7] * inv);
        *(float4*)&out[base + (size_t)i_g * DH + tx * 8]     = r0;
        *(float4*)&out[base + (size_t)i_g * DH + tx * 8 + 4] = r1;
    }
}

// ---------------- launch ----------------
extern "C" void kernel_launch(void* const* d_in, const int* in_sizes, int n_in,
                              void* d_out, int out_size) {
    const float* q = (const float*)d_in[0];
    const float* k = (const float*)d_in[1];
    const float* v = (const float*)d_in[2];
    float* out = (float*)d_out;

    pattern_kernel<<<dim3(LQ, NH), 128>>>(q, k);
    reduce_kernel<<<NH, 256>>>();
    topk_kernel<<<dim3(2, NH), 1024>>>();

    cudaFuncSetAttribute(flash_kernel,
                         cudaFuncAttributeMaxDynamicSharedMemorySize, SMEM_BYTES);
    flash_kernel<<<64 * NH, 256, SMEM_BYTES>>>(q, k, v, out);
}

// round 2
// speedup vs baseline: 1.3652x; 1.3652x over previous
#include <cuda_runtime.h>
#include <math.h>
#include <float.h>

#define NH 8
#define SEQ 4096
#define DH 128
#define LQ 64
#define VTOPK 1024
#define STOPK 2048
#define FORCE_V 30
#define FORCE_S 100
#define SCALE 0.08838834764831845f
#define NW (SEQ / 32)   // 128 mask words per head
#define QS_STRIDE 132   // padded Q row stride (floats)

// ---------------- device scratch ----------------
__device__ float    g_probs[NH * LQ * SEQ];      // unnormalized exp scores, 8 MB
__device__ float    g_vert [NH * SEQ];
__device__ float    g_slash[NH * SEQ];
__device__ unsigned g_vbits[NH * NW];
__device__ unsigned g_sbits[NH * NW];

// ---------------- cp.async helpers ----------------
__device__ __forceinline__ void cpa16(float* dst, const float* src) {
    unsigned d = (unsigned)__cvta_generic_to_shared(dst);
    asm volatile("cp.async.cg.shared.global [%0], [%1], 16;\n" :: "r"(d), "l"(src));
}
__device__ __forceinline__ void cpa_commit() { asm volatile("cp.async.commit_group;\n" ::); }
__device__ __forceinline__ void cpa_wait0()  { asm volatile("cp.async.wait_group 0;\n" ::); }

// ---------------- kernel A: exp-scores for last 64 queries (tiled GEMM) ----------------
__global__ void pattern_kernel(const float* __restrict__ q,
                               const float* __restrict__ k) {
    extern __shared__ float psm[];
    float* Qs = psm;                 // [64][132] padded, pre-scaled
    float* Ks = Qs + 64 * QS_STRIDE; // [128][128] swizzled
    int h  = blockIdx.y;
    int j0 = blockIdx.x * 128;
    int tid = threadIdx.x;           // 256
    int ty = tid >> 4, tx = tid & 15;

    for (int e = tid; e < 64 * 32; e += 256) {
        int r = e >> 5, c = e & 31;
        float4 t = *(const float4*)&q[((size_t)(h * SEQ + SEQ - LQ + r)) * DH + (c << 2)];
        t.x *= SCALE; t.y *= SCALE; t.z *= SCALE; t.w *= SCALE;
        *(float4*)&Qs[r * QS_STRIDE + (c << 2)] = t;
    }
    for (int e = tid; e < 128 * 32; e += 256) {
        int r = e >> 5, c = e & 31;
        *(float4*)&Ks[r * 128 + ((c ^ (r >> 2)) << 2)] =
            *(const float4*)&k[((size_t)(h * SEQ + j0 + r)) * DH + (c << 2)];
    }
    __syncthreads();

    float s[4][8];
    #pragma unroll
    for (int a = 0; a < 4; a++)
        #pragma unroll
        for (int b = 0; b < 8; b++) s[a][b] = 0.f;

    #pragma unroll 4
    for (int c = 0; c < 32; c++) {
        float4 qv[4], kv[8];
        #pragma unroll
        for (int a = 0; a < 4; a++)
            qv[a] = *(const float4*)&Qs[(ty * 4 + a) * QS_STRIDE + (c << 2)];
        #pragma unroll
        for (int b = 0; b < 8; b++) {
            int r = tx * 8 + b;
            kv[b] = *(const float4*)&Ks[r * 128 + ((c ^ (r >> 2)) << 2)];
        }
        #pragma unroll
        for (int a = 0; a < 4; a++)
            #pragma unroll
            for (int b = 0; b < 8; b++)
                s[a][b] += qv[a].x * kv[b].x + qv[a].y * kv[b].y
                         + qv[a].z * kv[b].z + qv[a].w * kv[b].w;
    }

    #pragma unroll
    for (int a = 0; a < 4; a++) {
        int row  = ty * 4 + a;
        int qpos = SEQ - LQ + row;
        float p[8];
        #pragma unroll
        for (int b = 0; b < 8; b++) {
            int j = j0 + tx * 8 + b;
            p[b] = (j <= qpos) ? __expf(s[a][b]) : 0.f;
        }
        float* dst = &g_probs[((size_t)(h * LQ + row)) * SEQ + j0 + tx * 8];
        *(float4*)&dst[0] = make_float4(p[0], p[1], p[2], p[3]);
        *(float4*)&dst[4] = make_float4(p[4], p[5], p[6], p[7]);
    }
}

// ---------------- kernel B: rowsums (deterministic) + vertical + slash ----------------
__global__ void reduce_kernel() {
    int h = blockIdx.x;
    int tid = threadIdx.x;  // 256
    __shared__ float part[256];
    __shared__ float inv[LQ];
    const float* pb = &g_probs[(size_t)h * LQ * SEQ];

    // deterministic row sums: 4 threads per row, fixed order
    {
        int r = tid >> 2, qd = tid & 3;
        const float* rowp = &pb[(size_t)r * SEQ];
        float sm = 0.f;
        for (int j = qd; j < SEQ; j += 4) sm += rowp[j];
        part[tid] = sm;
    }
    __syncthreads();
    if (tid < LQ)
        inv[tid] = 1.0f / (part[tid * 4] + part[tid * 4 + 1] +
                           part[tid * 4 + 2] + part[tid * 4 + 3]);
    __syncthreads();

    for (int j = tid; j < SEQ; j += 256) {
        float s = 0.f;
        #pragma unroll 8
        for (int lq = 0; lq < LQ; lq++) s += pb[(size_t)lq * SEQ + j] * inv[lq];
        g_vert[h * SEQ + j] = (j < FORCE_V) ? INFINITY : s;
    }
    for (int d = tid; d < SEQ; d += 256) {
        float s = 0.f;
        #pragma unroll 8
        for (int lq = 0; lq < LQ; lq++) {
            int idx = (SEQ - LQ) + lq - d;
            if (idx >= 0) s += pb[(size_t)lq * SEQ + idx] * inv[lq];
        }
        g_slash[h * SEQ + d] = (d < FORCE_S) ? INFINITY : s;
    }
}

// ---------------- kernel C: exact top-k -> bitmask (jax tie-break) ----------------
__global__ void topk_kernel() {
    int which = blockIdx.x;   // 0 = vertical, 1 = slash
    int h     = blockIdx.y;
    const float* arr = which ? &g_slash[h * SEQ] : &g_vert[h * SEQ];
    unsigned*   bits = which ? &g_sbits[h * NW]  : &g_vbits[h * NW];
    const int K = which ? STOPK : VTOPK;

    __shared__ unsigned long long keys[SEQ];  // 32 KB
    int tid = threadIdx.x;  // 1024

    if (tid < NW) bits[tid] = 0u;
    for (int i = tid; i < SEQ; i += 1024) {
        unsigned vb = __float_as_uint(arr[i]);   // values >= 0 -> monotonic bits
        keys[i] = ((unsigned long long)vb << 32) | (unsigned)(SEQ - 1 - i);
    }
    __syncthreads();

    for (int kk = 2; kk <= SEQ; kk <<= 1) {
        for (int j = kk >> 1; j > 0; j >>= 1) {
            for (int i = tid; i < SEQ; i += 1024) {
                int ixj = i ^ j;
                if (ixj > i) {
                    unsigned long long a = keys[i], b = keys[ixj];
                    bool up = ((i & kk) == 0);
                    if ((a > b) == up) { keys[i] = b; keys[ixj] = a; }
                }
            }
            __syncthreads();
        }
    }
    for (int t = tid; t < K; t += 1024) {
        int idx = (SEQ - 1) - (int)(keys[SEQ - 1 - t] & 0xffffffffu);
        atomicOr(&bits[idx >> 5], 1u << (idx & 31));
    }
}

// ---------------- kernel D: masked causal flash attention ----------------
// smem: Qs[64*132] + 4 KV buffers[8192 each] + Ps[4096] + masks
#define FL_SMEM_FLOATS (64 * QS_STRIDE + 4 * 8192 + 4096)
#define FL_SMEM_BYTES  (FL_SMEM_FLOATS * 4 + 2 * NW * 4)

__global__ void __launch_bounds__(256, 1)
flash_kernel(const float* __restrict__ q, const float* __restrict__ k,
             const float* __restrict__ v, float* __restrict__ out) {
    extern __shared__ float smem[];
    float* Qs = smem;                        // [64][132] padded, pre-scaled
    float* KV = Qs + 64 * QS_STRIDE;         // 4 buffers: K0 V0 K1 V1
    float* Ps = KV + 4 * 8192;               // [64][64]
    unsigned* vb = (unsigned*)(Ps + 64 * 64);
    unsigned* sb = vb + NW;

    int bid = blockIdx.x;
    int h  = bid & 7;
    int it = 63 - (bid >> 3);       // heavy tiles first
    int tid = threadIdx.x;
    int ty = tid >> 4, tx = tid & 15;

    if (tid < NW)            vb[tid]      = g_vbits[h * NW + tid];
    else if (tid < 2 * NW)   sb[tid - NW] = g_sbits[h * NW + tid - NW];

    const size_t base = (size_t)h * SEQ * DH;
    const int i0 = it * 64;

    // Q tile: unswizzled padded (reads are broadcast), pre-scaled
    for (int e = tid; e < 2048; e += 256) {
        int r = e >> 5, c = e & 31;
        float4 t = *(const float4*)&q[base + (size_t)(i0 + r) * DH + (c << 2)];
        t.x *= SCALE; t.y *= SCALE; t.z *= SCALE; t.w *= SCALE;
        *(float4*)&Qs[r * QS_STRIDE + (c << 2)] = t;
    }

    // preload jt=0 K/V via cp.async
    {
        float* Kb = KV; float* Vb = KV + 8192;
        for (int e = tid; e < 2048; e += 256) {
            int r = e >> 5, c = e & 31;
            int sw = r * 128 + ((c ^ (r >> 2)) << 2);
            size_t g = base + (size_t)r * DH + (c << 2);
            cpa16(&Kb[sw], &k[g]);
            cpa16(&Vb[sw], &v[g]);
        }
        cpa_commit();
    }

    float o[4][8];
    float l_i[4];
    #pragma unroll
    for (int a = 0; a < 4; a++) {
        l_i[a] = 0.f;
        #pragma unroll
        for (int cc = 0; cc < 8; cc++) o[a][cc] = 0.f;
    }

    for (int jt = 0; jt <= it; jt++) {
        cpa_wait0();
        __syncthreads();
        float* Kc = KV + (jt & 1) * 16384;
        float* Vc = Kc + 8192;

        // prefetch next tile
        if (jt < it) {
            float* Kn = KV + ((jt + 1) & 1) * 16384;
            float* Vn = Kn + 8192;
            size_t gb = base + (size_t)(jt + 1) * 64 * DH;
            for (int e = tid; e < 2048; e += 256) {
                int r = e >> 5, c = e & 31;
                int sw = r * 128 + ((c ^ (r >> 2)) << 2);
                size_t g = gb + (size_t)r * DH + (c << 2);
                cpa16(&Kn[sw], &k[g]);
                cpa16(&Vn[sw], &v[g]);
            }
            cpa_commit();
        }

        // ---- QK^T ----
        float s[4][4];
        #pragma unroll
        for (int a = 0; a < 4; a++)
            #pragma unroll
            for (int b = 0; b < 4; b++) s[a][b] = 0.f;

        const float* Qb  = Qs + (ty * 4) * QS_STRIDE;
        const float* Kb4 = Kc + (tx * 4) * 128;
        #pragma unroll 8
        for (int c = 0; c < 32; c++) {
            int kx = ((c ^ tx) << 2);
            float4 qv[4], kv[4];
            #pragma unroll
            for (int a = 0; a < 4; a++) qv[a] = *(const float4*)&Qb[a * QS_STRIDE + (c << 2)];
            #pragma unroll
            for (int b = 0; b < 4; b++) kv[b] = *(const float4*)&Kb4[b * 128 + kx];
            #pragma unroll
            for (int a = 0; a < 4; a++)
                #pragma unroll
                for (int b = 0; b < 4; b++)
                    s[a][b] += qv[a].x * kv[b].x + qv[a].y * kv[b].y
                             + qv[a].z * kv[b].z + qv[a].w * kv[b].w;
        }

        // ---- mask + exp (max-free), store P ----
        int j_g0 = jt * 64 + tx * 4;
        unsigned vnib = (vb[j_g0 >> 5] >> (j_g0 & 31)) & 0xFu;
        int D0 = i0 + ty * 4 - j_g0;     // d for (a=0,b=0)
        // slash bits for d = D0-3 .. D0+3 (7 values cover all (a,b))
        unsigned smask = 0;
        #pragma unroll
        for (int t = 0; t < 7; t++) {
            int dd = D0 - 3 + t;
            unsigned bit = (dd >= 0) ? ((sb[dd >> 5] >> (dd & 31)) & 1u) : 0u;
            smask |= bit << t;
        }
        #pragma unroll
        for (int a = 0; a < 4; a++) {
            float p[4]; float rs = 0.f;
            #pragma unroll
            for (int b = 0; b < 4; b++) {
                int d = D0 + a - b;
                bool ok = (d >= 0) &&
                          (((vnib >> b) & 1u) || ((smask >> (a - b + 3)) & 1u));
                float pe = ok ? __expf(s[a][b]) : 0.f;
                p[b] = pe; rs += pe;
            }
            l_i[a] += rs;
            *(float4*)&Ps[(ty * 4 + a) * 64 + ((tx ^ ty) << 2)] =
                make_float4(p[0], p[1], p[2], p[3]);
        }
        __syncthreads();

        // ---- P @ V ----
        #pragma unroll 4
        for (int kc = 0; kc < 16; kc++) {
            float4 pv[4];
            #pragma unroll
            for (int a = 0; a < 4; a++)
                pv[a] = *(const float4*)&Ps[(ty * 4 + a) * 64 + ((kc ^ ty) << 2)];
            #pragma unroll
            for (int u = 0; u < 4; u++) {
                int kk = kc * 4 + u;
                const float4 v0 = *(const float4*)&Vc[kk * 128 + (((2 * tx)     ^ (kk >> 2)) << 2)];
                const float4 v1 = *(const float4*)&Vc[kk * 128 + (((2 * tx + 1) ^ (kk >> 2)) << 2)];
                #pragma unroll
                for (int a = 0; a < 4; a++) {
                    float p = ((const float*)&pv[a])[u];
                    o[a][0] += p * v0.x; o[a][1] += p * v0.y;
                    o[a][2] += p * v0.z; o[a][3] += p * v0.w;
                    o[a][4] += p * v1.x; o[a][5] += p * v1.y;
                    o[a][6] += p * v1.z; o[a][7] += p * v1.w;
                }
            }
        }
    }

    // ---- epilogue: reduce l across the 16 lanes of each row, normalize, store ----
    #pragma unroll
    for (int a = 0; a < 4; a++) {
        float l = l_i[a];
        #pragma unroll
        for (int m = 1; m < 16; m <<= 1) l += __shfl_xor_sync(0xffffffffu, l, m);
        float inv = 1.0f / l;
        int i_g = i0 + ty * 4 + a;
        float4 r0 = make_float4(o[a][0] * inv, o[a][1] * inv, o[a][2] * inv, o[a][3] * inv);
        float4 r1 = make_float4(o[a][4] * inv, o[a][5] * inv, o[a][6] * inv, o[a][7] * inv);
        *(float4*)&out[base + (size_t)i_g * DH + tx * 8]     = r0;
        *(float4*)&out[base + (size_t)i_g * DH + tx * 8 + 4] = r1;
    }
}

// ---------------- launch ----------------
extern "C" void kernel_launch(void* const* d_in, const int* in_sizes, int n_in,
                              void* d_out, int out_size) {
    const float* q = (const float*)d_in[0];
    const float* k = (const float*)d_in[1];
    const float* v = (const float*)d_in[2];
    float* out = (float*)d_out;

    int psm = (64 * QS_STRIDE + 128 * 128) * 4;
    cudaFuncSetAttribute(pattern_kernel,
                         cudaFuncAttributeMaxDynamicSharedMemorySize, psm);
    pattern_kernel<<<dim3(SEQ / 128, NH), 256, psm>>>(q, k);
    reduce_kernel<<<NH, 256>>>();
    topk_kernel<<<dim3(2, NH), 1024>>>();

    cudaFuncSetAttribute(flash_kernel,
                         cudaFuncAttributeMaxDynamicSharedMemorySize, FL_SMEM_BYTES);
    flash_kernel<<<64 * NH, 256, FL_SMEM_BYTES>>>(q, k, v, out);
}